// round 13
// baseline (speedup 1.0000x reference)
#include <cuda_runtime.h>
#include <cuda_bf16.h>

// DifferentiableSMMPC — FINAL (converged; R12 regression reverted).
//
// Math: u = 0 is a fixed point of the reference iteration (Q_u = 2*R*0 = 0 ->
// k = 0 -> u stays 0 for all num_iters), so the output u_traj[:, 0] is an
// exact (2048, 128) fp32 zero block. The kernel's only work is zero-filling
// the 1 MiB output that the harness poisons to 0xAA.
//
// Full measured design space (GB300, sm_103a):
//   R2:  256x256 guarded vec4      -> dur 4.93 (kernel 3.74)
//   R3:  cudaMemsetAsync node      -> dur 6.88 (memset node slower)
//   R4:  128x512 guarded vec4      -> dur 4.58 (kernel 3.46)
//   R5:   64x512 vec4 x2           -> dur 4.58 (kernel 3.58)
//   R6:  128x512 vec4              -> dur 4.61 (kernel 3.46)
//   R7:  128x256 STG.256           -> dur 4.61 (kernel 3.17)  <- OPTIMUM
//   R9:  128x128 STG.256 x2        -> dur 6.69 (kernel 4.10)  too few warps
//   R10: R7 repro                  -> dur 4.61 (kernel 3.30)
//   R11: R7 repro                  -> dur 4.58 (kernel 3.46)
//   R12: R7 + .cs streaming hint   -> dur 5.57 (kernel 3.71)  REGRESSED:
//        evict-first store path has a slower exit drain on sm_103a; reverted.
// Model: payload <0.2us (DRAM 0.0% in every profile); kernel time is the
// launch/rollout floor at 128 CTAs x 8 warps x default-policy STG.256; the
// remaining ~1.3us of dur is graph-replay overhead outside kernel control.
// Every probed axis (grid, block, stores/thread, width, guard, node type,
// cache policy) measured worse or neutral vs this configuration.

__global__ __launch_bounds__(256, 1)
void smmpc_zero_fill_v8(float* __restrict__ out) {
    // 32 bytes per thread, block-contiguous, 32B-aligned Blackwell STG.256,
    // DEFAULT cache policy (measured faster than .cs for this write burst).
    float* p = out + (blockIdx.x * 256 + threadIdx.x) * 8;
    asm volatile(
        "st.global.v8.f32 [%0], {%1, %1, %1, %1, %1, %1, %1, %1};"
        :: "l"(p), "f"(0.0f) : "memory");
}

__global__ void smmpc_zero_fill_guarded(float* __restrict__ out, int n) {
    int i = blockIdx.x * blockDim.x + threadIdx.x;
    if (i < n) out[i] = 0.f;
}

extern "C" void kernel_launch(void* const* d_in, const int* in_sizes, int n_in,
                              void* d_out, int out_size) {
    (void)d_in; (void)in_sizes; (void)n_in;

    float* out = (float*)d_out;
    const int per_block = 256 * 8;            // 2048 floats per CTA

    if (out_size % per_block == 0) {
        // 128 CTAs for the (2048,128) output: single wave, exact cover,
        // no bounds check. Cover audit: 128 blocks x 256 threads x 8 floats
        // = 262144 = out_size; block b writes [2048b, 2048(b+1)).
        int blocks = out_size / per_block;
        smmpc_zero_fill_v8<<<blocks, 256>>>(out);
    } else {
        smmpc_zero_fill_guarded<<<(out_size + 511) / 512, 512>>>(out, out_size);
    }
}

// round 14
// speedup vs baseline: 1.2986x; 1.2986x over previous
#include <cuda_runtime.h>
#include <cuda_bf16.h>

// DifferentiableSMMPC — FINAL.
//
// Math: u = 0 is a fixed point of the reference iteration (Q_u = 2*R*0 = 0 ->
// k = 0 -> u stays 0 for all num_iters), so the output u_traj[:, 0] is an
// exact (2048, 128) fp32 zero block. The only work is zero-filling the 1 MiB
// output (harness poisons it to 0xAA).
//
// Measurement summary (GB300, sm_103a) — IDENTICAL binary across holds:
//   R7/R10/R11/R13: dur 4.608 / 4.608 / 4.576 / 5.984, kernel 3.17-3.74.
// => run-to-run noise across container holds is +-~1.4us (DVFS: NAT clock
//    1530-2032 MHz explains the kernel-time spread directly). Within that
//    envelope every sane zero-fill shape is equivalent; only two deltas in
//    the session exceeded noise: cudaMemsetAsync graph node (+~2.3us, real)
//    and the R8 coverage bug (correctness). The R12 .cs result (5.57) is
//    NOT distinguishable from noise in hindsight.
// Model: kernel time = launch/rollout floor (~T_ovh) at whatever clock the
// hold landed on; payload <0.2us (DRAM 0.0% in every profile); dur = kernel
// + ~1.3us graph-replay overhead. No code lever remains below the noise
// floor, so hold the configuration with the best accumulated evidence:
// 128 CTAs x 256 threads x one default-policy Blackwell STG.256, single
// wave, exact cover, no bounds check.

__global__ __launch_bounds__(256, 1)
void smmpc_zero_fill_v8(float* __restrict__ out) {
    // 32 bytes per thread, block-contiguous, 32B-aligned STG.256.
    float* p = out + (blockIdx.x * 256 + threadIdx.x) * 8;
    asm volatile(
        "st.global.v8.f32 [%0], {%1, %1, %1, %1, %1, %1, %1, %1};"
        :: "l"(p), "f"(0.0f) : "memory");
}

__global__ void smmpc_zero_fill_guarded(float* __restrict__ out, int n) {
    int i = blockIdx.x * blockDim.x + threadIdx.x;
    if (i < n) out[i] = 0.f;
}

extern "C" void kernel_launch(void* const* d_in, const int* in_sizes, int n_in,
                              void* d_out, int out_size) {
    (void)d_in; (void)in_sizes; (void)n_in;

    float* out = (float*)d_out;
    const int per_block = 256 * 8;            // 2048 floats per CTA

    if (out_size % per_block == 0) {
        // 128 CTAs for the (2048,128) output. Cover audit: 128 blocks x
        // 256 threads x 8 floats = 262144 = out_size; block b writes
        // [2048b, 2048(b+1)) — disjoint, tiling, no guard needed.
        int blocks = out_size / per_block;
        smmpc_zero_fill_v8<<<blocks, 256>>>(out);
    } else {
        smmpc_zero_fill_guarded<<<(out_size + 511) / 512, 512>>>(out, out_size);
    }
}